// round 1
// baseline (speedup 1.0000x reference)
#include <cuda_runtime.h>
#include <math.h>

#define NB 2
#define SN 512
#define DIM 256
#define NH 8
#define HD 32
// SCALE = 1/sqrt(32)
#define QSCALE 0.17677669529663689f
// ln(10000)/16
#define FREQC 0.5756462732485115f

// ---------------- scratch (device globals; no allocation allowed) -------------
__device__ float g_dist [NB*SN*SN];
__device__ float g_nodes[NB*SN*DIM];
__device__ float g_h    [NB*SN*DIM];
__device__ float g_qraw [NB*SN*DIM];
__device__ float g_kvraw[NB*SN*2*DIM];
__device__ float g_q    [NB*NH*SN*HD];   // [bh][i][d]  (rotary applied, *SCALE)
__device__ float g_kt   [NB*NH*HD*SN];   // [bh][d][i]  (rotary applied)
__device__ float g_v    [NB*NH*SN*HD];   // [bh][i][d]
__device__ float g_qwe  [NB*NH*SN];
__device__ float g_qbe  [NB*NH*SN];
__device__ float g_attno[NB*SN*DIM];     // [b][i][h*32+d]
__device__ float g_out  [NB*SN*DIM];

// ---------------- helpers ----------------
__device__ __forceinline__ float warpSum(float v){
    #pragma unroll
    for(int o=16;o;o>>=1) v += __shfl_xor_sync(0xffffffffu, v, o);
    return v;
}
__device__ __forceinline__ float warpMax(float v){
    #pragma unroll
    for(int o=16;o;o>>=1) v = fmaxf(v, __shfl_xor_sync(0xffffffffu, v, o));
    return v;
}

// ---------------- pairwise distances ----------------
__global__ void __launch_bounds__(256) k_dist(const float* __restrict__ x, float* __restrict__ dist){
    int idx = blockIdx.x*256 + threadIdx.x;          // < 2*512*512
    int j = idx & 511; int rest = idx >> 9;
    int i = rest & 511; int b = rest >> 9;
    const float* xi = x + (b*SN + i)*3;
    const float* xj = x + (b*SN + j)*3;
    float d0 = xi[0]-xj[0], d1 = xi[1]-xj[1], d2 = xi[2]-xj[2];
    float q = d0*d0 + d1*d1 + d2*d2;
    dist[idx] = (q > 0.f) ? sqrtf(q) : 0.f;
}

// ---------------- encoder: nodes = [x,t] @ W_enc ----------------
__global__ void __launch_bounds__(256) k_encode(const float* __restrict__ x, const float* __restrict__ t,
                                                const float* __restrict__ W, float* __restrict__ nodes){
    int idx = blockIdx.x*256 + threadIdx.x;          // < 1024*256
    int c = idx & 255; int tok = idx >> 8;
    const float* xp = x + tok*3;
    float v = xp[0]*W[c] + xp[1]*W[256+c] + xp[2]*W[512+c] + t[tok]*W[768+c];
    nodes[idx] = v;
}

// ---------------- layernorm (block per token) ----------------
__global__ void __launch_bounds__(256) k_ln(const float* __restrict__ x, const float* __restrict__ g,
                                            const float* __restrict__ b, float* __restrict__ y){
    int tok = blockIdx.x; int tid = threadIdx.x;
    float v = x[tok*DIM + tid];
    __shared__ float sred[8]; __shared__ float sb;
    int w = tid>>5, lane = tid&31;
    float s = warpSum(v);
    if(lane==0) sred[w] = s;
    __syncthreads();
    if(tid < 32){ float t2 = (tid<8)? sred[tid] : 0.f; t2 = warpSum(t2); if(tid==0) sb = t2; }
    __syncthreads();
    float mean = sb * (1.f/DIM);
    float d = v - mean;
    float s2 = warpSum(d*d);
    __syncthreads();
    if(lane==0) sred[w] = s2;
    __syncthreads();
    if(tid < 32){ float t2 = (tid<8)? sred[tid] : 0.f; t2 = warpSum(t2); if(tid==0) sb = t2; }
    __syncthreads();
    float var = sb * (1.f/DIM);
    y[tok*DIM + tid] = d * rsqrtf(var + 1e-5f) * g[tid] + b[tid];
}

// ---------------- generic small SGEMM: C[M,Nc] = A[M,K] @ W[K,Nc] + bias ----------------
__global__ void __launch_bounds__(256) k_gemm(const float* __restrict__ A, const float* __restrict__ W,
                                              const float* __restrict__ bias, float* __restrict__ C,
                                              int M, int Nc, int K){
    __shared__ __align__(16) float As[16][64];
    __shared__ __align__(16) float Bs[16][64];
    int tx = threadIdx.x;
    int bcol = blockIdx.x*64, brow = blockIdx.y*64;
    int tr = (tx>>4)<<2;
    int tc = (tx&15)<<2;
    float acc[4][4];
    #pragma unroll
    for(int u=0;u<4;u++) for(int vv=0;vv<4;vv++) acc[u][vv]=0.f;

    for(int k0=0;k0<K;k0+=16){
        #pragma unroll
        for(int i=tx;i<1024;i+=256){ int r=i>>4, c=i&15; As[c][r] = A[(brow+r)*K + k0 + c]; }
        #pragma unroll
        for(int i=tx;i<1024;i+=256){ int r=i>>6, c=i&63; Bs[r][c] = W[(k0+r)*Nc + bcol + c]; }
        __syncthreads();
        #pragma unroll
        for(int kk=0;kk<16;kk++){
            float4 a  = *(const float4*)&As[kk][tr];
            float4 bv = *(const float4*)&Bs[kk][tc];
            acc[0][0]=fmaf(a.x,bv.x,acc[0][0]); acc[0][1]=fmaf(a.x,bv.y,acc[0][1]);
            acc[0][2]=fmaf(a.x,bv.z,acc[0][2]); acc[0][3]=fmaf(a.x,bv.w,acc[0][3]);
            acc[1][0]=fmaf(a.y,bv.x,acc[1][0]); acc[1][1]=fmaf(a.y,bv.y,acc[1][1]);
            acc[1][2]=fmaf(a.y,bv.z,acc[1][2]); acc[1][3]=fmaf(a.y,bv.w,acc[1][3]);
            acc[2][0]=fmaf(a.z,bv.x,acc[2][0]); acc[2][1]=fmaf(a.z,bv.y,acc[2][1]);
            acc[2][2]=fmaf(a.z,bv.z,acc[2][2]); acc[2][3]=fmaf(a.z,bv.w,acc[2][3]);
            acc[3][0]=fmaf(a.w,bv.x,acc[3][0]); acc[3][1]=fmaf(a.w,bv.y,acc[3][1]);
            acc[3][2]=fmaf(a.w,bv.z,acc[3][2]); acc[3][3]=fmaf(a.w,bv.w,acc[3][3]);
        }
        __syncthreads();
    }
    #pragma unroll
    for(int u=0;u<4;u++){
        #pragma unroll
        for(int vv=0;vv<4;vv++){
            int col = bcol + tc + vv;
            C[(brow+tr+u)*Nc + col] = acc[u][vv] + bias[col];
        }
    }
}

// ---------------- rotary on Q + precompute q.We and q.be (scaled) ----------------
__global__ void __launch_bounds__(256) k_rotq(const float* __restrict__ qraw, const float* __restrict__ We,
                                              const float* __restrict__ be, float* __restrict__ q,
                                              float* __restrict__ qwe, float* __restrict__ qbe){
    int bi = blockIdx.x;                  // b*512 + i
    int b = bi >> 9, i = bi & 511;
    int h = threadIdx.x >> 5, d = threadIdx.x & 31;
    const float* row = qraw + bi*DIM;
    float v = row[h*32 + d];
    float other = row[h*32 + ((d+16)&31)];
    float rot = (d < 16) ? -other : other;
    int fd = d & 15;
    float fr = (float)i * expf(-(float)fd * FREQC);
    float val = (v*cosf(fr) + rot*sinf(fr)) * QSCALE;
    int bh = b*NH + h;
    q[(bh*SN + i)*HD + d] = val;
    float dwe = warpSum(val * We[h*32 + d]);
    float dbe = warpSum(val * be[h*32 + d]);
    if(d == 0){ qwe[bh*SN + i] = dwe; qbe[bh*SN + i] = dbe; }
}

// ---------------- rotary on K (write transposed) + relayout V ----------------
__global__ void __launch_bounds__(256) k_rotkv(const float* __restrict__ kvraw, float* __restrict__ kt,
                                               float* __restrict__ v){
    int bi = blockIdx.x;
    int b = bi >> 9, i = bi & 511;
    int h = threadIdx.x >> 5, d = threadIdx.x & 31;
    const float* row = kvraw + bi*(2*DIM);
    float kv = row[h*32 + d];
    float other = row[h*32 + ((d+16)&31)];
    float rot = (d < 16) ? -other : other;
    int fd = d & 15;
    float fr = (float)i * expf(-(float)fd * FREQC);
    float kval = kv*cosf(fr) + rot*sinf(fr);
    int bh = b*NH + h;
    kt[(bh*HD + d)*SN + i] = kval;
    v[(bh*SN + i)*HD + d]  = row[DIM + h*32 + d];
}

// ---------------- attention: warp per query row ----------------
__global__ void __launch_bounds__(256) k_attn(
    const float* __restrict__ q, const float* __restrict__ kt, const float* __restrict__ v,
    const float* __restrict__ qwe, const float* __restrict__ qbe, const float* __restrict__ dist,
    const float* __restrict__ We, const float* __restrict__ be, float* __restrict__ out)
{
    __shared__ __align__(16) float sp[8][512];
    int w = threadIdx.x >> 5, lane = threadIdx.x & 31;
    int bh = blockIdx.x >> 6;            // 0..15
    int chunk = blockIdx.x & 63;
    int b = bh >> 3, h = bh & 7;
    int i = chunk*8 + w;

    // broadcast q row into registers
    float qr[32];
    {
        float qv = q[(bh*SN + i)*HD + lane];
        #pragma unroll
        for(int d=0;d<32;d++) qr[d] = __shfl_sync(0xffffffffu, qv, d);
    }
    float cwe = qwe[bh*SN + i];
    float cbe = qbe[bh*SN + i];
    const float* Kt = kt + bh*HD*SN;
    const float* Dr = dist + (b*SN + i)*SN;

    float m = -1e30f;
    #pragma unroll
    for(int cb=0;cb<4;cb++){
        int j0 = cb*128 + lane*4;
        float4 s = make_float4(cbe,cbe,cbe,cbe);
        #pragma unroll
        for(int d=0;d<32;d++){
            float4 kk = *(const float4*)(Kt + d*SN + j0);
            s.x = fmaf(qr[d], kk.x, s.x);
            s.y = fmaf(qr[d], kk.y, s.y);
            s.z = fmaf(qr[d], kk.z, s.z);
            s.w = fmaf(qr[d], kk.w, s.w);
        }
        float4 dd = *(const float4*)(Dr + j0);
        s.x = fmaf(dd.x, cwe, s.x);
        s.y = fmaf(dd.y, cwe, s.y);
        s.z = fmaf(dd.z, cwe, s.z);
        s.w = fmaf(dd.w, cwe, s.w);
        *(float4*)&sp[w][j0] = s;
        m = fmaxf(m, fmaxf(fmaxf(s.x,s.y), fmaxf(s.z,s.w)));
    }
    m = warpMax(m);

    float sum = 0.f, sd = 0.f;
    #pragma unroll
    for(int cb=0;cb<4;cb++){
        int j0 = cb*128 + lane*4;
        float4 s = *(const float4*)&sp[w][j0];
        float4 dd = *(const float4*)(Dr + j0);
        float4 p;
        p.x = __expf(s.x - m); p.y = __expf(s.y - m);
        p.z = __expf(s.z - m); p.w = __expf(s.w - m);
        sum += (p.x + p.y) + (p.z + p.w);
        sd  = fmaf(p.x, dd.x, sd); sd = fmaf(p.y, dd.y, sd);
        sd  = fmaf(p.z, dd.z, sd); sd = fmaf(p.w, dd.w, sd);
        *(float4*)&sp[w][j0] = p;
    }
    sum = warpSum(sum);
    sd  = warpSum(sd);
    float inv = 1.f / sum;
    __syncwarp();

    // pass 2: lane = output dim d
    const float* Vp = v + bh*SN*HD;
    const float4* sp4 = (const float4*)sp[w];
    float acc = 0.f;
    #pragma unroll 4
    for(int j4=0;j4<128;j4++){
        float4 p = sp4[j4];
        const float* vb = Vp + j4*128 + lane;
        acc = fmaf(p.x, vb[0],  acc);
        acc = fmaf(p.y, vb[32], acc);
        acc = fmaf(p.z, vb[64], acc);
        acc = fmaf(p.w, vb[96], acc);
    }
    float sdn = sd * inv;
    float o = acc*inv + sdn*We[h*32 + lane] + be[h*32 + lane];
    out[((b*SN + i)*NH + h)*HD + lane] = o;
}

// ---------------- fused gate + residual (warp per token), in-place nodes update --------
__global__ void __launch_bounds__(256) k_gate(const float* __restrict__ o, const float* __restrict__ wg,
                                              float* __restrict__ nodes){
    int w = threadIdx.x >> 5, lane = threadIdx.x & 31;
    int tok = blockIdx.x*8 + w;
    const float* op = o + tok*DIM;
    float* np = nodes + tok*DIM;
    float s = 0.f;
    #pragma unroll
    for(int k=0;k<8;k++){
        int c = lane + k*32;
        float ov = op[c], nv = np[c];
        s = fmaf(ov, wg[c] + wg[512+c], s);
        s = fmaf(nv, wg[256+c] - wg[512+c], s);
    }
    s = warpSum(s);
    float g = 1.f / (1.f + __expf(-s));
    #pragma unroll
    for(int k=0;k<8;k++){
        int c = lane + k*32;
        float ov = op[c], nv = np[c];
        np[c] = ov*g + nv*(1.f - g);
    }
}

// ---------------- decoder: out = nodes @ W_dec [256,3] ----------------
__global__ void __launch_bounds__(256) k_decode(const float* __restrict__ nodes, const float* __restrict__ Wd,
                                                float* __restrict__ out){
    int w = threadIdx.x >> 5, lane = threadIdx.x & 31;
    int tok = blockIdx.x*8 + w;
    const float* np = nodes + tok*DIM;
    float a0 = 0.f, a1 = 0.f, a2 = 0.f;
    #pragma unroll
    for(int k0=0;k0<8;k0++){
        int k = lane + k0*32;
        float nv = np[k];
        a0 = fmaf(nv, Wd[k*3+0], a0);
        a1 = fmaf(nv, Wd[k*3+1], a1);
        a2 = fmaf(nv, Wd[k*3+2], a2);
    }
    a0 = warpSum(a0); a1 = warpSum(a1); a2 = warpSum(a2);
    if(lane == 0){
        out[tok*3+0] = a0; out[tok*3+1] = a1; out[tok*3+2] = a2;
    }
}

// ---------------- launch ----------------
extern "C" void kernel_launch(void* const* d_in, const int* in_sizes, int n_in,
                              void* d_out, int out_size){
    (void)in_sizes; (void)n_in; (void)out_size;
    const float* x     = (const float*)d_in[0];
    const float* t     = (const float*)d_in[1];
    const float* W_enc = (const float*)d_in[2];
    const float* W_dec = (const float*)d_in[3];
    const float* ln_g  = (const float*)d_in[4];
    const float* ln_b  = (const float*)d_in[5];
    const float* Wq    = (const float*)d_in[6];
    const float* bq    = (const float*)d_in[7];
    const float* Wkv   = (const float*)d_in[8];
    const float* bkv   = (const float*)d_in[9];
    const float* We    = (const float*)d_in[10];
    const float* be    = (const float*)d_in[11];
    const float* Wo    = (const float*)d_in[12];
    const float* bo    = (const float*)d_in[13];
    const float* Wg    = (const float*)d_in[14];
    float* out = (float*)d_out;

    float *dist,*nodes,*h,*qraw,*kvraw,*q,*kt,*v,*qwe,*qbe,*attno,*ofull;
    cudaGetSymbolAddress((void**)&dist,  g_dist);
    cudaGetSymbolAddress((void**)&nodes, g_nodes);
    cudaGetSymbolAddress((void**)&h,     g_h);
    cudaGetSymbolAddress((void**)&qraw,  g_qraw);
    cudaGetSymbolAddress((void**)&kvraw, g_kvraw);
    cudaGetSymbolAddress((void**)&q,     g_q);
    cudaGetSymbolAddress((void**)&kt,    g_kt);
    cudaGetSymbolAddress((void**)&v,     g_v);
    cudaGetSymbolAddress((void**)&qwe,   g_qwe);
    cudaGetSymbolAddress((void**)&qbe,   g_qbe);
    cudaGetSymbolAddress((void**)&attno, g_attno);
    cudaGetSymbolAddress((void**)&ofull, g_out);

    k_dist  <<<2048,256>>>(x, dist);
    k_encode<<<1024,256>>>(x, t, W_enc, nodes);

    for(int l=0;l<2;l++){
        k_ln<<<1024,256>>>(nodes, ln_g + l*DIM, ln_b + l*DIM, h);
        dim3 gq(4,16), gkv(8,16);
        k_gemm<<<gq,256>>>(h, Wq  + l*DIM*DIM,   bq  + l*DIM,   qraw,  1024, 256, 256);
        k_gemm<<<gkv,256>>>(h, Wkv + l*DIM*2*DIM, bkv + l*2*DIM, kvraw, 1024, 512, 256);
        k_rotq <<<1024,256>>>(qraw, We + l*DIM, be + l*DIM, q, qwe, qbe);
        k_rotkv<<<1024,256>>>(kvraw, kt, v);
        k_attn <<<1024,256>>>(q, kt, v, qwe, qbe, dist, We + l*DIM, be + l*DIM, attno);
        k_gemm<<<gq,256>>>(attno, Wo + l*DIM*DIM, bo + l*DIM, ofull, 1024, 256, 256);
        k_gate<<<128,256>>>(ofull, Wg + l*3*DIM, nodes);
    }
    k_decode<<<128,256>>>(nodes, W_dec, out);
}

// round 2
// speedup vs baseline: 1.4496x; 1.4496x over previous
#include <cuda_runtime.h>
#include <math.h>

#define NB 2
#define SN 512
#define DIM 256
#define NH 8
#define HD 32
#define QSCALE 0.17677669529663689f   // 1/sqrt(32)
#define FREQC  0.5756462732485115f    // ln(10000)/16

// ---------------- scratch (device globals) ----------------
__device__ float g_dist [NB*SN*SN];
__device__ float g_nodes[NB*SN*DIM];
__device__ float g_h    [NB*SN*DIM];
__device__ float g_qkv  [NB*SN*3*DIM];   // [tok][768] : q | k | v
__device__ float g_q    [NB*NH*SN*HD];   // [bh][i][d] rotary, *SCALE
__device__ float g_kt   [NB*NH*HD*SN];   // [bh][d][i] rotary
__device__ float g_v    [NB*NH*SN*HD];   // [bh][i][d]
__device__ float g_qwe  [NB*NH*SN];
__device__ float g_qbe  [NB*NH*SN];
__device__ float g_attno[NB*SN*DIM];
__device__ float g_out  [NB*SN*DIM];

// ---------------- helpers ----------------
__device__ __forceinline__ float warpSum(float v){
    #pragma unroll
    for(int o=16;o;o>>=1) v += __shfl_xor_sync(0xffffffffu, v, o);
    return v;
}
__device__ __forceinline__ float warpMax(float v){
    #pragma unroll
    for(int o=16;o;o>>=1) v = fmaxf(v, __shfl_xor_sync(0xffffffffu, v, o));
    return v;
}

// ---------------- pairwise distances ----------------
__global__ void __launch_bounds__(256) k_dist(const float* __restrict__ x, float* __restrict__ dist){
    int idx = blockIdx.x*256 + threadIdx.x;
    int j = idx & 511; int rest = idx >> 9;
    int i = rest & 511; int b = rest >> 9;
    const float* xi = x + (b*SN + i)*3;
    const float* xj = x + (b*SN + j)*3;
    float d0 = xi[0]-xj[0], d1 = xi[1]-xj[1], d2 = xi[2]-xj[2];
    float q = d0*d0 + d1*d1 + d2*d2;
    dist[idx] = (q > 0.f) ? sqrtf(q) : 0.f;
}

// ---------------- encoder ----------------
__global__ void __launch_bounds__(256) k_encode(const float* __restrict__ x, const float* __restrict__ t,
                                                const float* __restrict__ W, float* __restrict__ nodes){
    int idx = blockIdx.x*256 + threadIdx.x;
    int c = idx & 255; int tok = idx >> 8;
    const float* xp = x + tok*3;
    nodes[idx] = xp[0]*W[c] + xp[1]*W[256+c] + xp[2]*W[512+c] + t[tok]*W[768+c];
}

// ---------------- layernorm ----------------
__global__ void __launch_bounds__(256) k_ln(const float* __restrict__ x, const float* __restrict__ g,
                                            const float* __restrict__ b, float* __restrict__ y){
    int tok = blockIdx.x; int tid = threadIdx.x;
    float v = x[tok*DIM + tid];
    __shared__ float sred[8]; __shared__ float sb;
    int w = tid>>5, lane = tid&31;
    float s = warpSum(v);
    if(lane==0) sred[w] = s;
    __syncthreads();
    if(tid < 32){ float t2 = (tid<8)? sred[tid] : 0.f; t2 = warpSum(t2); if(tid==0) sb = t2; }
    __syncthreads();
    float mean = sb * (1.f/DIM);
    float d = v - mean;
    float s2 = warpSum(d*d);
    __syncthreads();
    if(lane==0) sred[w] = s2;
    __syncthreads();
    if(tid < 32){ float t2 = (tid<8)? sred[tid] : 0.f; t2 = warpSum(t2); if(tid==0) sb = t2; }
    __syncthreads();
    float var = sb * (1.f/DIM);
    y[tok*DIM + tid] = d * rsqrtf(var + 1e-5f) * g[tid] + b[tid];
}

// ============ double-buffered SGEMM core (BNx64 tiles, BK=32) ============
// A [M,K] row-major (lda=K), W [K,Nc], C [M,ldc], bias per global col.

template<int BM>
__global__ void __launch_bounds__(256) k_gemm2(const float* __restrict__ A, const float* __restrict__ W,
                                               const float* __restrict__ bias, float* __restrict__ C,
                                               int Nc, int K, int ldc){
    constexpr int BK = 32, BN = 64;
    constexpr int LA = (BM*BK/4)/256;   // 2 (BM=64) or 1 (BM=32)
    constexpr int RPT = BM/16;          // 4 or 2
    __shared__ float As[2][BM][BK+1];
    __shared__ __align__(16) float Bs[2][BK][BN];
    int tx = threadIdx.x;
    int bcol = blockIdx.x*BN, brow = blockIdx.y*BM;

    int am[LA], ak[LA];
    #pragma unroll
    for(int u=0;u<LA;u++){ int f = tx + u*256; am[u]=f>>3; ak[u]=(f&7)*4; }
    int brd[2], bcd[2];
    #pragma unroll
    for(int u=0;u<2;u++){ int f = tx + u*256; brd[u]=f>>4; bcd[u]=(f&15)*4; }

    const float* Ab = A + brow*K;
    const float* Wb = W + bcol;

    float4 ra[LA], rb[2];
    #pragma unroll
    for(int u=0;u<LA;u++) ra[u] = *(const float4*)(Ab + am[u]*K + ak[u]);
    #pragma unroll
    for(int u=0;u<2;u++)  rb[u] = *(const float4*)(Wb + brd[u]*Nc + bcd[u]);
    #pragma unroll
    for(int u=0;u<LA;u++){
        As[0][am[u]][ak[u]+0]=ra[u].x; As[0][am[u]][ak[u]+1]=ra[u].y;
        As[0][am[u]][ak[u]+2]=ra[u].z; As[0][am[u]][ak[u]+3]=ra[u].w;
    }
    #pragma unroll
    for(int u=0;u<2;u++) *(float4*)&Bs[0][brd[u]][bcd[u]] = rb[u];
    __syncthreads();

    int tcc = (tx&15)*4;
    int trr = (tx>>4)*RPT;
    float acc[RPT][4];
    #pragma unroll
    for(int u=0;u<RPT;u++){ acc[u][0]=0.f; acc[u][1]=0.f; acc[u][2]=0.f; acc[u][3]=0.f; }

    int NT = K/BK;
    for(int t=0;t<NT;t++){
        int buf = t&1;
        if(t+1<NT){
            int k0 = (t+1)*BK;
            #pragma unroll
            for(int u=0;u<LA;u++) ra[u] = *(const float4*)(Ab + am[u]*K + k0 + ak[u]);
            #pragma unroll
            for(int u=0;u<2;u++)  rb[u] = *(const float4*)(Wb + (k0+brd[u])*Nc + bcd[u]);
        }
        #pragma unroll
        for(int kk=0;kk<BK;kk++){
            float4 b = *(const float4*)&Bs[buf][kk][tcc];
            float a[RPT];
            #pragma unroll
            for(int u=0;u<RPT;u++) a[u] = As[buf][trr+u][kk];
            #pragma unroll
            for(int u=0;u<RPT;u++){
                acc[u][0]=fmaf(a[u],b.x,acc[u][0]);
                acc[u][1]=fmaf(a[u],b.y,acc[u][1]);
                acc[u][2]=fmaf(a[u],b.z,acc[u][2]);
                acc[u][3]=fmaf(a[u],b.w,acc[u][3]);
            }
        }
        if(t+1<NT){
            int nb = buf^1;
            #pragma unroll
            for(int u=0;u<LA;u++){
                As[nb][am[u]][ak[u]+0]=ra[u].x; As[nb][am[u]][ak[u]+1]=ra[u].y;
                As[nb][am[u]][ak[u]+2]=ra[u].z; As[nb][am[u]][ak[u]+3]=ra[u].w;
            }
            #pragma unroll
            for(int u=0;u<2;u++) *(float4*)&Bs[nb][brd[u]][bcd[u]] = rb[u];
            __syncthreads();
        }
    }
    #pragma unroll
    for(int u=0;u<RPT;u++){
        #pragma unroll
        for(int vv=0;vv<4;vv++){
            int col = bcol + tcc + vv;
            C[(brow+trr+u)*ldc + col] = acc[u][vv] + bias[col];
        }
    }
}

// QKV fused: columns [0,256) from Wq/bq, [256,768) from Wkv/bkv. C is [1024,768].
__global__ void __launch_bounds__(256) k_gemm_qkv(const float* __restrict__ A,
                                                  const float* __restrict__ Wq, const float* __restrict__ bq,
                                                  const float* __restrict__ Wkv, const float* __restrict__ bkv,
                                                  float* __restrict__ C){
    constexpr int BM=64, BK=32, BN=64, K=256;
    __shared__ float As[2][BM][BK+1];
    __shared__ __align__(16) float Bs[2][BK][BN];
    int tx = threadIdx.x;
    int bcol = blockIdx.x*BN, brow = blockIdx.y*BM;

    const float* W; const float* bias; int ldb;
    if(bcol < 256){ W = Wq + bcol;        bias = bq + bcol;        ldb = 256; }
    else          { W = Wkv + (bcol-256); bias = bkv + (bcol-256); ldb = 512; }

    int am[2], ak[2];
    #pragma unroll
    for(int u=0;u<2;u++){ int f = tx + u*256; am[u]=f>>3; ak[u]=(f&7)*4; }
    int brd[2], bcd[2];
    #pragma unroll
    for(int u=0;u<2;u++){ int f = tx + u*256; brd[u]=f>>4; bcd[u]=(f&15)*4; }

    const float* Ab = A + brow*K;

    float4 ra[2], rb[2];
    #pragma unroll
    for(int u=0;u<2;u++) ra[u] = *(const float4*)(Ab + am[u]*K + ak[u]);
    #pragma unroll
    for(int u=0;u<2;u++) rb[u] = *(const float4*)(W + brd[u]*ldb + bcd[u]);
    #pragma unroll
    for(int u=0;u<2;u++){
        As[0][am[u]][ak[u]+0]=ra[u].x; As[0][am[u]][ak[u]+1]=ra[u].y;
        As[0][am[u]][ak[u]+2]=ra[u].z; As[0][am[u]][ak[u]+3]=ra[u].w;
    }
    #pragma unroll
    for(int u=0;u<2;u++) *(float4*)&Bs[0][brd[u]][bcd[u]] = rb[u];
    __syncthreads();

    int tcc = (tx&15)*4;
    int trr = (tx>>4)*4;
    float acc[4][4];
    #pragma unroll
    for(int u=0;u<4;u++){ acc[u][0]=0.f; acc[u][1]=0.f; acc[u][2]=0.f; acc[u][3]=0.f; }

    const int NT = K/BK;   // 8
    for(int t=0;t<NT;t++){
        int buf = t&1;
        if(t+1<NT){
            int k0 = (t+1)*BK;
            #pragma unroll
            for(int u=0;u<2;u++) ra[u] = *(const float4*)(Ab + am[u]*K + k0 + ak[u]);
            #pragma unroll
            for(int u=0;u<2;u++) rb[u] = *(const float4*)(W + (k0+brd[u])*ldb + bcd[u]);
        }
        #pragma unroll
        for(int kk=0;kk<BK;kk++){
            float4 b = *(const float4*)&Bs[buf][kk][tcc];
            float a[4];
            #pragma unroll
            for(int u=0;u<4;u++) a[u] = As[buf][trr+u][kk];
            #pragma unroll
            for(int u=0;u<4;u++){
                acc[u][0]=fmaf(a[u],b.x,acc[u][0]);
                acc[u][1]=fmaf(a[u],b.y,acc[u][1]);
                acc[u][2]=fmaf(a[u],b.z,acc[u][2]);
                acc[u][3]=fmaf(a[u],b.w,acc[u][3]);
            }
        }
        if(t+1<NT){
            int nb = buf^1;
            #pragma unroll
            for(int u=0;u<2;u++){
                As[nb][am[u]][ak[u]+0]=ra[u].x; As[nb][am[u]][ak[u]+1]=ra[u].y;
                As[nb][am[u]][ak[u]+2]=ra[u].z; As[nb][am[u]][ak[u]+3]=ra[u].w;
            }
            #pragma unroll
            for(int u=0;u<2;u++) *(float4*)&Bs[nb][brd[u]][bcd[u]] = rb[u];
            __syncthreads();
        }
    }
    #pragma unroll
    for(int u=0;u<4;u++){
        #pragma unroll
        for(int vv=0;vv<4;vv++){
            int lc = tcc + vv;
            C[(brow+trr+u)*768 + bcol + lc] = acc[u][vv] + bias[lc];
        }
    }
}

// ---------------- rotary Q/K (+ q.We, q.be precompute) + V relayout ----------------
__global__ void __launch_bounds__(256) k_rot(const float* __restrict__ qkv,
                                             const float* __restrict__ We, const float* __restrict__ be,
                                             float* __restrict__ q, float* __restrict__ qwe, float* __restrict__ qbe,
                                             float* __restrict__ kt, float* __restrict__ v){
    int bi = blockIdx.x;
    int b = bi >> 9, i = bi & 511;
    int h = threadIdx.x >> 5, d = threadIdx.x & 31;
    int bh = b*NH + h;
    const float* row = qkv + bi*768;
    float fr = (float)i * expf(-(float)(d & 15) * FREQC);
    float cs = cosf(fr), sn = sinf(fr);

    float qv = row[h*32 + d];
    float qo = row[h*32 + ((d+16)&31)];
    float qrot = (d < 16) ? -qo : qo;
    float qval = (qv*cs + qrot*sn) * QSCALE;
    q[(bh*SN + i)*HD + d] = qval;

    float kv = row[256 + h*32 + d];
    float ko = row[256 + h*32 + ((d+16)&31)];
    float krot = (d < 16) ? -ko : ko;
    kt[(bh*HD + d)*SN + i] = kv*cs + krot*sn;

    v[(bh*SN + i)*HD + d] = row[512 + h*32 + d];

    float dwe = warpSum(qval * We[h*32 + d]);
    float dbe = warpSum(qval * be[h*32 + d]);
    if(d == 0){ qwe[bh*SN + i] = dwe; qbe[bh*SN + i] = dbe; }
}

// ---------------- attention: warp handles 2 query rows ----------------
__global__ void __launch_bounds__(256) k_attn2(
    const float* __restrict__ q, const float* __restrict__ kt, const float* __restrict__ v,
    const float* __restrict__ qwe, const float* __restrict__ qbe, const float* __restrict__ dist,
    const float* __restrict__ We, const float* __restrict__ be, float* __restrict__ out)
{
    __shared__ __align__(16) float sp[16][512];
    int w = threadIdx.x >> 5, lane = threadIdx.x & 31;
    int bh = blockIdx.x >> 5;            // 16 bh
    int chunk = blockIdx.x & 31;         // 32 chunks x 16 rows
    int b = bh >> 3, h = bh & 7;
    int i0 = chunk*16 + w*2, i1 = i0 + 1;

    float qr0[32], qr1[32];
    {
        float qv0 = q[(bh*SN + i0)*HD + lane];
        float qv1 = q[(bh*SN + i1)*HD + lane];
        #pragma unroll
        for(int d=0;d<32;d++){ qr0[d] = __shfl_sync(0xffffffffu, qv0, d);
                               qr1[d] = __shfl_sync(0xffffffffu, qv1, d); }
    }
    float cwe0 = qwe[bh*SN + i0], cwe1 = qwe[bh*SN + i1];
    float cbe0 = qbe[bh*SN + i0], cbe1 = qbe[bh*SN + i1];
    const float* Kt = kt + bh*HD*SN;
    const float* D0 = dist + (b*SN + i0)*SN;
    const float* D1 = dist + (b*SN + i1)*SN;

    float m0 = -1e30f, m1 = -1e30f;
    #pragma unroll
    for(int cb=0;cb<4;cb++){
        int j0 = cb*128 + lane*4;
        float4 s0 = make_float4(cbe0,cbe0,cbe0,cbe0);
        float4 s1 = make_float4(cbe1,cbe1,cbe1,cbe1);
        #pragma unroll
        for(int d=0;d<32;d++){
            float4 kk = *(const float4*)(Kt + d*SN + j0);
            s0.x = fmaf(qr0[d], kk.x, s0.x); s0.y = fmaf(qr0[d], kk.y, s0.y);
            s0.z = fmaf(qr0[d], kk.z, s0.z); s0.w = fmaf(qr0[d], kk.w, s0.w);
            s1.x = fmaf(qr1[d], kk.x, s1.x); s1.y = fmaf(qr1[d], kk.y, s1.y);
            s1.z = fmaf(qr1[d], kk.z, s1.z); s1.w = fmaf(qr1[d], kk.w, s1.w);
        }
        float4 d0 = *(const float4*)(D0 + j0);
        float4 d1 = *(const float4*)(D1 + j0);
        s0.x = fmaf(d0.x, cwe0, s0.x); s0.y = fmaf(d0.y, cwe0, s0.y);
        s0.z = fmaf(d0.z, cwe0, s0.z); s0.w = fmaf(d0.w, cwe0, s0.w);
        s1.x = fmaf(d1.x, cwe1, s1.x); s1.y = fmaf(d1.y, cwe1, s1.y);
        s1.z = fmaf(d1.z, cwe1, s1.z); s1.w = fmaf(d1.w, cwe1, s1.w);
        *(float4*)&sp[w*2  ][j0] = s0;
        *(float4*)&sp[w*2+1][j0] = s1;
        m0 = fmaxf(m0, fmaxf(fmaxf(s0.x,s0.y), fmaxf(s0.z,s0.w)));
        m1 = fmaxf(m1, fmaxf(fmaxf(s1.x,s1.y), fmaxf(s1.z,s1.w)));
    }
    m0 = warpMax(m0); m1 = warpMax(m1);

    float sum0 = 0.f, sum1 = 0.f, sd0 = 0.f, sd1 = 0.f;
    #pragma unroll
    for(int cb=0;cb<4;cb++){
        int j0 = cb*128 + lane*4;
        float4 s0 = *(const float4*)&sp[w*2  ][j0];
        float4 s1 = *(const float4*)&sp[w*2+1][j0];
        float4 d0 = *(const float4*)(D0 + j0);
        float4 d1 = *(const float4*)(D1 + j0);
        float4 p0, p1;
        p0.x = __expf(s0.x-m0); p0.y = __expf(s0.y-m0); p0.z = __expf(s0.z-m0); p0.w = __expf(s0.w-m0);
        p1.x = __expf(s1.x-m1); p1.y = __expf(s1.y-m1); p1.z = __expf(s1.z-m1); p1.w = __expf(s1.w-m1);
        sum0 += (p0.x+p0.y)+(p0.z+p0.w);
        sum1 += (p1.x+p1.y)+(p1.z+p1.w);
        sd0 = fmaf(p0.x,d0.x,sd0); sd0 = fmaf(p0.y,d0.y,sd0); sd0 = fmaf(p0.z,d0.z,sd0); sd0 = fmaf(p0.w,d0.w,sd0);
        sd1 = fmaf(p1.x,d1.x,sd1); sd1 = fmaf(p1.y,d1.y,sd1); sd1 = fmaf(p1.z,d1.z,sd1); sd1 = fmaf(p1.w,d1.w,sd1);
        *(float4*)&sp[w*2  ][j0] = p0;
        *(float4*)&sp[w*2+1][j0] = p1;
    }
    sum0 = warpSum(sum0); sum1 = warpSum(sum1);
    sd0  = warpSum(sd0);  sd1  = warpSum(sd1);
    float inv0 = 1.f/sum0, inv1 = 1.f/sum1;
    __syncwarp();

    const float* Vp = v + bh*SN*HD;
    const float4* p0v = (const float4*)sp[w*2];
    const float4* p1v = (const float4*)sp[w*2+1];
    float a0 = 0.f, a1 = 0.f;
    #pragma unroll 4
    for(int j4=0;j4<128;j4++){
        float4 p0 = p0v[j4];
        float4 p1 = p1v[j4];
        const float* vb = Vp + j4*128 + lane;
        float v0 = vb[0], v1 = vb[32], v2 = vb[64], v3 = vb[96];
        a0 = fmaf(p0.x,v0,a0); a0 = fmaf(p0.y,v1,a0); a0 = fmaf(p0.z,v2,a0); a0 = fmaf(p0.w,v3,a0);
        a1 = fmaf(p1.x,v0,a1); a1 = fmaf(p1.y,v1,a1); a1 = fmaf(p1.z,v2,a1); a1 = fmaf(p1.w,v3,a1);
    }
    float wl = We[h*32 + lane], bl = be[h*32 + lane];
    out[((b*SN + i0)*NH + h)*HD + lane] = a0*inv0 + (sd0*inv0)*wl + bl;
    out[((b*SN + i1)*NH + h)*HD + lane] = a1*inv1 + (sd1*inv1)*wl + bl;
}

// ---------------- fused gate + residual ----------------
__global__ void __launch_bounds__(256) k_gate(const float* __restrict__ o, const float* __restrict__ wg,
                                              float* __restrict__ nodes){
    int w = threadIdx.x >> 5, lane = threadIdx.x & 31;
    int tok = blockIdx.x*8 + w;
    const float* op = o + tok*DIM;
    float* np = nodes + tok*DIM;
    float s = 0.f;
    #pragma unroll
    for(int k=0;k<8;k++){
        int c = lane + k*32;
        float ov = op[c], nv = np[c];
        s = fmaf(ov, wg[c] + wg[512+c], s);
        s = fmaf(nv, wg[256+c] - wg[512+c], s);
    }
    s = warpSum(s);
    float g = 1.f / (1.f + __expf(-s));
    #pragma unroll
    for(int k=0;k<8;k++){
        int c = lane + k*32;
        float ov = op[c], nv = np[c];
        np[c] = ov*g + nv*(1.f - g);
    }
}

// ---------------- decoder ----------------
__global__ void __launch_bounds__(256) k_decode(const float* __restrict__ nodes, const float* __restrict__ Wd,
                                                float* __restrict__ out){
    int w = threadIdx.x >> 5, lane = threadIdx.x & 31;
    int tok = blockIdx.x*8 + w;
    const float* np = nodes + tok*DIM;
    float a0 = 0.f, a1 = 0.f, a2 = 0.f;
    #pragma unroll
    for(int k0=0;k0<8;k0++){
        int k = lane + k0*32;
        float nv = np[k];
        a0 = fmaf(nv, Wd[k*3+0], a0);
        a1 = fmaf(nv, Wd[k*3+1], a1);
        a2 = fmaf(nv, Wd[k*3+2], a2);
    }
    a0 = warpSum(a0); a1 = warpSum(a1); a2 = warpSum(a2);
    if(lane == 0){
        out[tok*3+0] = a0; out[tok*3+1] = a1; out[tok*3+2] = a2;
    }
}

// ---------------- launch ----------------
extern "C" void kernel_launch(void* const* d_in, const int* in_sizes, int n_in,
                              void* d_out, int out_size){
    (void)in_sizes; (void)n_in; (void)out_size;
    const float* x     = (const float*)d_in[0];
    const float* t     = (const float*)d_in[1];
    const float* W_enc = (const float*)d_in[2];
    const float* W_dec = (const float*)d_in[3];
    const float* ln_g  = (const float*)d_in[4];
    const float* ln_b  = (const float*)d_in[5];
    const float* Wq    = (const float*)d_in[6];
    const float* bq    = (const float*)d_in[7];
    const float* Wkv   = (const float*)d_in[8];
    const float* bkv   = (const float*)d_in[9];
    const float* We    = (const float*)d_in[10];
    const float* be    = (const float*)d_in[11];
    const float* Wo    = (const float*)d_in[12];
    const float* bo    = (const float*)d_in[13];
    const float* Wg    = (const float*)d_in[14];
    float* out = (float*)d_out;

    float *dist,*nodes,*h,*qkv,*q,*kt,*v,*qwe,*qbe,*attno,*ofull;
    cudaGetSymbolAddress((void**)&dist,  g_dist);
    cudaGetSymbolAddress((void**)&nodes, g_nodes);
    cudaGetSymbolAddress((void**)&h,     g_h);
    cudaGetSymbolAddress((void**)&qkv,   g_qkv);
    cudaGetSymbolAddress((void**)&q,     g_q);
    cudaGetSymbolAddress((void**)&kt,    g_kt);
    cudaGetSymbolAddress((void**)&v,     g_v);
    cudaGetSymbolAddress((void**)&qwe,   g_qwe);
    cudaGetSymbolAddress((void**)&qbe,   g_qbe);
    cudaGetSymbolAddress((void**)&attno, g_attno);
    cudaGetSymbolAddress((void**)&ofull, g_out);

    k_dist  <<<2048,256>>>(x, dist);
    k_encode<<<1024,256>>>(x, t, W_enc, nodes);

    for(int l=0;l<2;l++){
        k_ln<<<1024,256>>>(nodes, ln_g + l*DIM, ln_b + l*DIM, h);
        k_gemm_qkv<<<dim3(12,16),256>>>(h, Wq + l*DIM*DIM, bq + l*DIM,
                                        Wkv + l*DIM*2*DIM, bkv + l*2*DIM, qkv);
        k_rot<<<1024,256>>>(qkv, We + l*DIM, be + l*DIM, q, qwe, qbe, kt, v);
        k_attn2<<<512,256>>>(q, kt, v, qwe, qbe, dist, We + l*DIM, be + l*DIM, attno);
        k_gemm2<32><<<dim3(4,32),256>>>(attno, Wo + l*DIM*DIM, bo + l*DIM, ofull, 256, 256, 256);
        k_gate<<<128,256>>>(ofull, Wg + l*3*DIM, nodes);
    }
    k_decode<<<128,256>>>(nodes, W_dec, out);
}